// round 14
// baseline (speedup 1.0000x reference)
#include <cuda_runtime.h>
#include <cuda_fp16.h>
#include <cstdint>
#include <math.h>

#define BSZ 8
#define NPTS 2048
#define KNN 20
#define EPS 1e-5f
#define SLOPE 0.2f

// ---------------- scratch (device globals) ----------------
__device__ float g_S[(long)BSZ * NPTS * NPTS];
__device__ float g_d2[BSZ * NPTS];
__device__ int   g_idx[BSZ * NPTS * KNN];
__device__ float g_YZ[(long)BSZ * NPTS * 512];
__device__ float g_pmax[128 * 1024];
__device__ float g_psum[128 * 1024];
__device__ float g_g[BSZ * 2048];
__device__ float g_h1[BSZ * 512];
__device__ float g_h2[BSZ * 256];
// unified feature hi/lo (ld = 512): columns 0..511 = [x1 | x2 | x3 | x4]
__device__ __align__(16) unsigned short g_XCh[(long)BSZ * NPTS * 512];
__device__ __align__(16) unsigned short g_XCl[(long)BSZ * NPTS * 512];
__device__ __align__(16) unsigned short g_W5h[1024 * 512];
__device__ __align__(16) unsigned short g_W5l[1024 * 512];
__device__ __align__(16) unsigned short g_Wh[90112];
__device__ __align__(16) unsigned short g_Wl[90112];

__device__ __forceinline__ uint32_t smem_u32(const void* p) {
    uint32_t a;
    asm("{ .reg .u64 t; cvta.to.shared.u64 t, %1; cvt.u32.u64 %0, t; }" : "=r"(a) : "l"(p));
    return a;
}

#define LDSM4(f, addr) \
    asm volatile("ldmatrix.sync.aligned.m8n8.x4.shared.b16 {%0,%1,%2,%3}, [%4];" \
                 : "=r"((f)[0]), "=r"((f)[1]), "=r"((f)[2]), "=r"((f)[3]) : "r"(addr))

#define MMA16816(c, a, b0, b1) \
    asm volatile("mma.sync.aligned.m16n8k16.row.col.f32.f16.f16.f32 " \
                 "{%0,%1,%2,%3}, {%4,%5,%6,%7}, {%8,%9}, {%0,%1,%2,%3};" \
                 : "+f"((c)[0]), "+f"((c)[1]), "+f"((c)[2]), "+f"((c)[3]) \
                 : "r"((a)[0]), "r"((a)[1]), "r"((a)[2]), "r"((a)[3]), "r"(b0), "r"(b1))

#define CPA16(dst, src) \
    asm volatile("cp.async.ca.shared.global [%0], [%1], 16;" :: "r"(dst), "l"(src))
#define CPA_COMMIT() asm volatile("cp.async.commit_group;" ::: "memory")
#define CPA_WAIT0() asm volatile("cp.async.wait_group 0;" ::: "memory")
#define CPA_WAIT1() asm volatile("cp.async.wait_group 1;" ::: "memory")

// ======================= HMMA split-fp16 GEMM (double-buffered cp.async) ===========
// C = A(MxK, row-stride ldA) * B(NxK, row-stride ldB)^T, fp16 hi/lo.
// npass: 2 = hh+hl; 3 = hh+hl+lh.
// mode 0: raw; 1: 2v-d2[col]; 2: bn+leakyrelu; 3: bn+act + pooled partials.
#define GSM_BUF 8192
#define GSM_TOTAL (2 * 4 * GSM_BUF + 2048)

__global__ __launch_bounds__(256, 2) void gemm_mma(
        const unsigned short* __restrict__ Ah0, const unsigned short* __restrict__ Al0,
        int ldA, long bsA,
        const unsigned short* __restrict__ Bh0, const unsigned short* __restrict__ Bl0,
        int ldB, long bsB,
        float* __restrict__ Cm, int ldc, long bsC,
        int K, const float* __restrict__ d2, const float* __restrict__ bnp,
        int Nn, int mode, int npass,
        float* __restrict__ pmax, float* __restrict__ psum) {
    extern __shared__ __align__(16) char dyn[];
    float* redm = (float*)(dyn + 2 * 4 * GSM_BUF);
    float* reds = redm + 256;

    int tid = threadIdx.x, wid = tid >> 5, lane = tid & 31;
    int bm = blockIdx.y * 128, bn = blockIdx.x * 128, z = blockIdx.z;

    const unsigned short* Ah = Ah0 + (long)z * bsA;
    const unsigned short* Al = Al0 + (long)z * bsA;
    const unsigned short* Bh = Bh0 + (long)z * bsB;
    const unsigned short* Bl = Bl0 + (long)z * bsB;

    int wm = (wid >> 2) * 64, wn = (wid & 3) * 32;
    int a_r = lane & 15, a_kh = lane >> 4;
    int b_n = (lane & 7) + ((lane >> 4) << 3), b_kh = (lane >> 3) & 1;

    uint32_t ub = smem_u32(dyn);

    int r0 = tid >> 2, ci0 = tid & 3;
    int r1 = (tid + 256) >> 2, ci1 = (tid + 256) & 3;
    int ph0 = r0 * 64 + ((ci0 ^ ((r0 >> 1) & 3)) * 16);
    int ph1 = r1 * 64 + ((ci1 ^ ((r1 >> 1) & 3)) * 16);

    int nch = K >> 5;

#define LOAD_CHUNK(bufi, k0_) do { \
    uint32_t o = ub + (bufi) * 4 * GSM_BUF; \
    long gA0 = (long)(bm + r0) * ldA + (k0_) + ci0 * 8; \
    long gA1 = (long)(bm + r1) * ldA + (k0_) + ci1 * 8; \
    long gB0 = (long)(bn + r0) * ldB + (k0_) + ci0 * 8; \
    long gB1 = (long)(bn + r1) * ldB + (k0_) + ci1 * 8; \
    CPA16(o + ph0, Ah + gA0);                 CPA16(o + ph1, Ah + gA1); \
    CPA16(o + 2 * GSM_BUF + ph0, Bh + gB0);   CPA16(o + 2 * GSM_BUF + ph1, Bh + gB1); \
    CPA16(o + GSM_BUF + ph0, Al + gA0);       CPA16(o + GSM_BUF + ph1, Al + gA1); \
    CPA16(o + 3 * GSM_BUF + ph0, Bl + gB0);   CPA16(o + 3 * GSM_BUF + ph1, Bl + gB1); \
    CPA_COMMIT(); \
} while (0)

    float acc[4][4][4] = {};

    LOAD_CHUNK(0, 0);
    for (int ch = 0; ch < nch; ch++) {
        if (ch + 1 < nch) {
            LOAD_CHUNK((ch + 1) & 1, (ch + 1) << 5);
            CPA_WAIT1();
        } else {
            CPA_WAIT0();
        }
        __syncthreads();
        uint32_t o = ub + (ch & 1) * 4 * GSM_BUF;
        uint32_t sAh = o, sAl = o + GSM_BUF, sBh = o + 2 * GSM_BUF, sBl = o + 3 * GSM_BUF;
#pragma unroll
        for (int s = 0; s < 2; s++) {
            uint32_t af[4][4], bfh[2][4], bfl[2][4];
#pragma unroll
            for (int mt = 0; mt < 4; mt++) {
                int row = wm + mt * 16 + a_r;
                int chh = 2 * s + a_kh;
                LDSM4(af[mt], sAh + row * 64 + ((chh ^ ((row >> 1) & 3)) * 16));
            }
#pragma unroll
            for (int g = 0; g < 2; g++) {
                int row = wn + g * 16 + b_n;
                int chh = 2 * s + b_kh;
                LDSM4(bfh[g], sBh + row * 64 + ((chh ^ ((row >> 1) & 3)) * 16));
            }
#pragma unroll
            for (int mt = 0; mt < 4; mt++)
#pragma unroll
                for (int nt = 0; nt < 4; nt++)
                    MMA16816(acc[mt][nt], af[mt], bfh[nt >> 1][(nt & 1) * 2], bfh[nt >> 1][(nt & 1) * 2 + 1]);
#pragma unroll
            for (int g = 0; g < 2; g++) {
                int row = wn + g * 16 + b_n;
                int chh = 2 * s + b_kh;
                LDSM4(bfl[g], sBl + row * 64 + ((chh ^ ((row >> 1) & 3)) * 16));
            }
#pragma unroll
            for (int mt = 0; mt < 4; mt++)
#pragma unroll
                for (int nt = 0; nt < 4; nt++)
                    MMA16816(acc[mt][nt], af[mt], bfl[nt >> 1][(nt & 1) * 2], bfl[nt >> 1][(nt & 1) * 2 + 1]);
            if (npass > 2) {
#pragma unroll
                for (int mt = 0; mt < 4; mt++) {
                    int row = wm + mt * 16 + a_r;
                    int chh = 2 * s + a_kh;
                    LDSM4(af[mt], sAl + row * 64 + ((chh ^ ((row >> 1) & 3)) * 16));
                }
#pragma unroll
                for (int mt = 0; mt < 4; mt++)
#pragma unroll
                    for (int nt = 0; nt < 4; nt++)
                        MMA16816(acc[mt][nt], af[mt], bfh[nt >> 1][(nt & 1) * 2], bfh[nt >> 1][(nt & 1) * 2 + 1]);
            }
        }
        __syncthreads();
    }

    if (mode == 3) {
        float cmax[8], csum[8];
#pragma unroll
        for (int q = 0; q < 8; q++) { cmax[q] = -INFINITY; csum[q] = 0.f; }
#pragma unroll
        for (int mt = 0; mt < 4; mt++)
#pragma unroll
            for (int h = 0; h < 2; h++)
#pragma unroll
                for (int nt = 0; nt < 4; nt++)
#pragma unroll
                    for (int j = 0; j < 2; j++) {
                        int col = bn + wn + nt * 8 + (lane & 3) * 2 + j;
                        float v = acc[mt][nt][h * 2 + j];
                        float gg = bnp[col], be = bnp[Nn + col];
                        float mm = bnp[2 * Nn + col], vv = bnp[3 * Nn + col];
                        v = (v - mm) * (gg * rsqrtf(vv + EPS)) + be;
                        v = v > 0.f ? v : SLOPE * v;
                        int q = nt * 2 + j;
                        cmax[q] = fmaxf(cmax[q], v);
                        csum[q] += v;
                    }
#pragma unroll
        for (int q = 0; q < 8; q++) {
#pragma unroll
            for (int off = 4; off < 32; off <<= 1) {
                cmax[q] = fmaxf(cmax[q], __shfl_xor_sync(0xffffffffu, cmax[q], off));
                csum[q] += __shfl_xor_sync(0xffffffffu, csum[q], off);
            }
        }
        if ((lane >> 2) == 0) {
            int g = wid >> 2;
#pragma unroll
            for (int nt = 0; nt < 4; nt++)
#pragma unroll
                for (int j = 0; j < 2; j++) {
                    int cl = wn + nt * 8 + (lane & 3) * 2 + j;
                    redm[g * 128 + cl] = cmax[nt * 2 + j];
                    reds[g * 128 + cl] = csum[nt * 2 + j];
                }
        }
        __syncthreads();
        if (tid < 128) {
            pmax[(long)blockIdx.y * 1024 + bn + tid] = fmaxf(redm[tid], redm[128 + tid]);
            psum[(long)blockIdx.y * 1024 + bn + tid] = reds[tid] + reds[128 + tid];
        }
        return;
    }

    float* Cb = Cm + (long)z * bsC;
#pragma unroll
    for (int mt = 0; mt < 4; mt++) {
        int rr = bm + wm + mt * 16 + (lane >> 2);
#pragma unroll
        for (int h = 0; h < 2; h++) {
            int row = rr + h * 8;
#pragma unroll
            for (int nt = 0; nt < 4; nt++) {
                int col = bn + wn + nt * 8 + (lane & 3) * 2;
                float v0 = acc[mt][nt][h * 2];
                float v1 = acc[mt][nt][h * 2 + 1];
                if (mode == 1) {
                    const float* dd = d2 + (long)z * NPTS;
                    v0 = 2.f * v0 - dd[col];
                    v1 = 2.f * v1 - dd[col + 1];
                } else if (mode == 2) {
                    float gg = bnp[col], be = bnp[Nn + col];
                    float mm = bnp[2 * Nn + col], vv = bnp[3 * Nn + col];
                    v0 = (v0 - mm) * (gg * rsqrtf(vv + EPS)) + be;
                    v0 = v0 > 0.f ? v0 : SLOPE * v0;
                    gg = bnp[col + 1]; be = bnp[Nn + col + 1];
                    mm = bnp[2 * Nn + col + 1]; vv = bnp[3 * Nn + col + 1];
                    v1 = (v1 - mm) * (gg * rsqrtf(vv + EPS)) + be;
                    v1 = v1 > 0.f ? v1 : SLOPE * v1;
                }
                *(float2*)&Cb[(long)row * ldc + col] = make_float2(v0, v1);
            }
        }
    }
}

// ======================= pool reduce =======================
__global__ void pool_reduce(const float* __restrict__ pmax, const float* __restrict__ psum,
                            float* __restrict__ gb) {
    int c = blockIdx.x * 256 + threadIdx.x;
    int b = blockIdx.y;
    float m = -INFINITY, s = 0.f;
#pragma unroll
    for (int i = 0; i < 16; i++) {
        int by = b * 16 + i;
        m = fmaxf(m, pmax[(long)by * 1024 + c]);
        s += psum[(long)by * 1024 + c];
    }
    gb[b * 2048 + c] = m;
    gb[b * 2048 + 1024 + c] = s * (1.0f / NPTS);
}

// ======================= fused layer-1 YZ + d2 (K=3) =======================
__global__ __launch_bounds__(256) void l1yz_d2(
        const float* __restrict__ x, const float* __restrict__ w1,
        float* __restrict__ YZ, float* __restrict__ d2) {
    __shared__ float wf[128][3];
    int tid = threadIdx.x;
    if (tid < 128) {
        int o = tid & 63;
        if (tid < 64) {
            wf[tid][0] = w1[o * 6 + 0];
            wf[tid][1] = w1[o * 6 + 1];
            wf[tid][2] = w1[o * 6 + 2];
        } else {
            wf[tid][0] = w1[o * 6 + 3] - w1[o * 6 + 0];
            wf[tid][1] = w1[o * 6 + 4] - w1[o * 6 + 1];
            wf[tid][2] = w1[o * 6 + 5] - w1[o * 6 + 2];
        }
    }
    __syncthreads();
    long i = (long)blockIdx.x * 256 + tid;
    int n = (int)(i >> 7), o = (int)(i & 127);
    float x0 = x[n * 3], x1 = x[n * 3 + 1], x2 = x[n * 3 + 2];
    YZ[i] = x0 * wf[o][0] + x1 * wf[o][1] + x2 * wf[o][2];
    if (o == 0) d2[n] = x0 * x0 + x1 * x1 + x2 * x2;
}

// ======================= d2 + split (weights only) =======================
__global__ void d2split_kernel(const float* __restrict__ src, int ld, int C, int rows,
                               unsigned short* __restrict__ hi, unsigned short* __restrict__ lo,
                               float* __restrict__ d2) {
    int row = blockIdx.x * 8 + (threadIdx.x >> 5);
    int lane = threadIdx.x & 31;
    if (row >= rows) return;
    const float* xr = src + (long)row * ld;
    float s = 0.f;
    for (int c = lane; c < C; c += 32) {
        float v = xr[c];
        s += v * v;
        __half h = __float2half_rn(v);
        __half l = __float2half_rn(v - __half2float(h));
        hi[(long)row * C + c] = *(unsigned short*)&h;
        lo[(long)row * C + c] = *(unsigned short*)&l;
    }
    if (d2) {
#pragma unroll
        for (int o = 16; o; o >>= 1) s += __shfl_xor_sync(0xffffffffu, s, o);
        if (lane == 0) d2[row] = s;
    }
}

__global__ void make_weff_split(const float* __restrict__ w, int O, int C,
                                unsigned short* __restrict__ hi, unsigned short* __restrict__ lo) {
    int i = blockIdx.x * blockDim.x + threadIdx.x;
    if (i >= 2 * O * C) return;
    int row = i / C, c = i % C;
    float v;
    if (row < O) v = w[row * 2 * C + c];
    else { int o = row - O; v = w[o * 2 * C + C + c] - w[o * 2 * C + c]; }
    __half h = __float2half_rn(v);
    __half l = __float2half_rn(v - __half2float(h));
    hi[i] = *(unsigned short*)&h;
    lo[i] = *(unsigned short*)&l;
}

// ======================= fp32 SIMT GEMM (layer 1 gram) =======================
#define BM 128
#define BN 128
#define BK 8
__global__ __launch_bounds__(256) void gemm_abT(
        const float* __restrict__ A, int lda, long bsA,
        const float* __restrict__ Bm, int ldb, long bsB,
        float* __restrict__ Cm, int ldc, long bsC,
        int M, int Nn, int K,
        const float* __restrict__ d2, long bsD2, int mode) {
    const float* Ab = A + (long)blockIdx.z * bsA;
    const float* Bb = Bm + (long)blockIdx.z * bsB;
    float* Cb = Cm + (long)blockIdx.z * bsC;

    __shared__ float As[BK][BM + 4];
    __shared__ float Bs[BK][BN + 4];

    int tid = threadIdx.x;
    int tx = tid & 15, ty = tid >> 4;
    int bm = blockIdx.y * BM, bn = blockIdx.x * BN;
    int lk = tid & 7, lm = tid >> 3;

    float ra[4], rb[4];
    float acc[8][8] = {};

#pragma unroll
    for (int i = 0; i < 4; i++) {
        int m = lm + i * 32;
        ra[i] = (lk < K) ? Ab[(long)(bm + m) * lda + lk] : 0.f;
        rb[i] = (lk < K) ? Bb[(long)(bn + m) * ldb + lk] : 0.f;
    }

    for (int k0 = 0; k0 < K; k0 += BK) {
#pragma unroll
        for (int i = 0; i < 4; i++) {
            As[lk][lm + i * 32] = ra[i];
            Bs[lk][lm + i * 32] = rb[i];
        }
        __syncthreads();
        int kn = k0 + BK;
        if (kn < K) {
#pragma unroll
            for (int i = 0; i < 4; i++) {
                int m = lm + i * 32;
                ra[i] = (kn + lk < K) ? Ab[(long)(bm + m) * lda + kn + lk] : 0.f;
                rb[i] = (kn + lk < K) ? Bb[(long)(bn + m) * ldb + kn + lk] : 0.f;
            }
        }
#pragma unroll
        for (int kk = 0; kk < BK; kk++) {
            float4 a0 = *(const float4*)&As[kk][ty * 4];
            float4 a1 = *(const float4*)&As[kk][64 + ty * 4];
            float4 b0 = *(const float4*)&Bs[kk][tx * 4];
            float4 b1 = *(const float4*)&Bs[kk][64 + tx * 4];
            float av[8] = {a0.x, a0.y, a0.z, a0.w, a1.x, a1.y, a1.z, a1.w};
            float bv[8] = {b0.x, b0.y, b0.z, b0.w, b1.x, b1.y, b1.z, b1.w};
#pragma unroll
            for (int i = 0; i < 8; i++)
#pragma unroll
                for (int j = 0; j < 8; j++) acc[i][j] += av[i] * bv[j];
        }
        __syncthreads();
    }

#pragma unroll
    for (int i = 0; i < 8; i++) {
        int m = bm + (i < 4 ? ty * 4 + i : 64 + ty * 4 + (i - 4));
#pragma unroll
        for (int j = 0; j < 8; j++) {
            int n_ = bn + (j < 4 ? tx * 4 + j : 64 + tx * 4 + (j - 4));
            float v = acc[i][j];
            if (mode == 1) v = 2.f * v - d2[(long)blockIdx.z * bsD2 + n_];
            Cb[(long)m * ldc + n_] = v;
        }
    }
}

// ---------------- top-k: one warp per row, smem values + group-max register cache ----
#define TOPK_SMEM (8 * 2048 * 4)
__global__ __launch_bounds__(256) void topk_kernel(const float* __restrict__ S,
                                                   int* __restrict__ idxo) {
    extern __shared__ float sv_all[];
    int warp = threadIdx.x >> 5, lane = threadIdx.x & 31;
    int row = blockIdx.x * 8 + warp;
    float* sv = sv_all + warp * 2048;
    const float* s = S + (long)row * NPTS;

    float gmax[8];
    int gj[8];
#pragma unroll
    for (int g = 0; g < 8; g++) {
        float bm = -INFINITY;
        int bj = g * 8;
#pragma unroll
        for (int e = 0; e < 8; e++) {
            int j = g * 8 + e;
            float v = s[j * 32 + lane];
            sv[j * 32 + lane] = v;
            if (v > bm) { bm = v; bj = j; }
        }
        gmax[g] = bm; gj[g] = bj;
    }

    for (int it = 0; it < KNN; it++) {
        float best = gmax[0];
        int bj = gj[0];
#pragma unroll
        for (int g = 1; g < 8; g++)
            if (gmax[g] > best) { best = gmax[g]; bj = gj[g]; }
        int bidx = bj * 32 + lane;
        float wb = best;
        int wi = bidx;
#pragma unroll
        for (int o = 16; o; o >>= 1) {
            float ov = __shfl_down_sync(0xffffffffu, wb, o);
            int oi = __shfl_down_sync(0xffffffffu, wi, o);
            if (ov > wb || (ov == wb && oi < wi)) { wb = ov; wi = oi; }
        }
        wi = __shfl_sync(0xffffffffu, wi, 0);
        if (lane == 0) idxo[(long)row * KNN + it] = wi;
        if ((wi & 31) == lane) {
            int j = wi >> 5;
            int g = j >> 3;
            sv[j * 32 + lane] = -INFINITY;
            float bm = -INFINITY;
            int bjn = g * 8;
            for (int e = 0; e < 8; e++) {
                int jj = g * 8 + e;
                float v = sv[jj * 32 + lane];
                if (v > bm) { bm = v; bjn = jj; }
            }
#pragma unroll
            for (int gg = 0; gg < 8; gg++)
                if (gg == g) { gmax[gg] = bm; gj[gg] = bjn; }
        }
    }
}

// ---------------- gather + max + bn + act + fp16 split + d2 emit ----------------
__global__ void gather_max(const float* __restrict__ YZ, int twoO,
                           const int* __restrict__ idxi,
                           const float* __restrict__ bnp,
                           unsigned short* __restrict__ hi, unsigned short* __restrict__ lo,
                           int outoff, float* __restrict__ d2, int O) {
    int n = blockIdx.x, b = blockIdx.y, o = threadIdx.x;
    __shared__ int si[KNN];
    __shared__ float red[8];
    if (o < KNN) si[o] = idxi[((long)b * NPTS + n) * KNN + o];
    __syncthreads();
    const float* Yb = YZ + (long)b * NPTS * twoO;
    float m = -INFINITY;
#pragma unroll 4
    for (int k = 0; k < KNN; k++) m = fmaxf(m, Yb[(long)si[k] * twoO + o]);
    float z = Yb[(long)n * twoO + O + o];
    float t = m + z;
    float gg = bnp[o], be = bnp[O + o], mm = bnp[2 * O + o], vv = bnp[3 * O + o];
    float v = (t - mm) * (gg * rsqrtf(vv + EPS)) + be;
    v = v > 0.f ? v : SLOPE * v;
    long base = ((long)b * NPTS + n) * 512 + outoff + o;
    __half h = __float2half_rn(v);
    __half l2 = __float2half_rn(v - __half2float(h));
    hi[base] = *(unsigned short*)&h;
    lo[base] = *(unsigned short*)&l2;
    if (d2) {
        float s = v * v;
#pragma unroll
        for (int off = 16; off; off >>= 1) s += __shfl_down_sync(0xffffffffu, s, off);
        if ((o & 31) == 0) red[o >> 5] = s;
        __syncthreads();
        if (o == 0) {
            float tot = 0.f;
            for (int w = 0; w < (O >> 5); w++) tot += red[w];
            d2[b * NPTS + n] = tot;
        }
    }
}

// ---------------- small FC ----------------
__global__ void fc_kernel(const float* __restrict__ in, int K,
                          const float* __restrict__ W,
                          const float* __restrict__ bias,
                          const float* __restrict__ bnp, int useAct,
                          float* __restrict__ out, int O) {
    int o = blockIdx.x, b = blockIdx.y, t = threadIdx.x;
    const float* xr = in + (long)b * K;
    const float* wr = W + (long)o * K;
    float s = 0.f;
    for (int k = t; k < K; k += 128) s += xr[k] * wr[k];
    __shared__ float red[4];
#pragma unroll
    for (int off = 16; off; off >>= 1) s += __shfl_down_sync(0xffffffffu, s, off);
    if ((t & 31) == 0) red[t >> 5] = s;
    __syncthreads();
    if (t == 0) {
        float tot = red[0] + red[1] + red[2] + red[3];
        if (bias) tot += bias[o];
        if (bnp) {
            float gg = bnp[o], be = bnp[O + o], mm = bnp[2 * O + o], vv = bnp[3 * O + o];
            tot = (tot - mm) * (gg * rsqrtf(vv + EPS)) + be;
        }
        if (useAct) tot = tot > 0.f ? tot : SLOPE * tot;
        out[(long)b * O + o] = tot;
    }
}

extern "C" void kernel_launch(void* const* d_in, const int* in_sizes, int n_in,
                              void* d_out, int out_size) {
    const float* x   = (const float*)d_in[0];
    const float* w1  = (const float*)d_in[2];
    const float* w2  = (const float*)d_in[3];
    const float* w3  = (const float*)d_in[4];
    const float* w4  = (const float*)d_in[5];
    const float* w5  = (const float*)d_in[6];
    const float* wl1 = (const float*)d_in[7];
    const float* wl2 = (const float*)d_in[8];
    const float* bl2 = (const float*)d_in[9];
    const float* wl3 = (const float*)d_in[10];
    const float* bl3 = (const float*)d_in[11];
    const float* bn1 = (const float*)d_in[12];
    const float* bn2 = (const float*)d_in[13];
    const float* bn3 = (const float*)d_in[14];
    const float* bn4 = (const float*)d_in[15];
    const float* bn5 = (const float*)d_in[16];
    const float* bn6 = (const float*)d_in[17];
    const float* bn7 = (const float*)d_in[18];

    float *S, *d2, *YZ, *pmax, *psum, *gb, *h1, *h2;
    int* idx;
    unsigned short *XCh, *XCl, *W5h, *W5l, *Wh, *Wl;
    cudaGetSymbolAddress((void**)&S, g_S);
    cudaGetSymbolAddress((void**)&d2, g_d2);
    cudaGetSymbolAddress((void**)&idx, g_idx);
    cudaGetSymbolAddress((void**)&YZ, g_YZ);
    cudaGetSymbolAddress((void**)&pmax, g_pmax);
    cudaGetSymbolAddress((void**)&psum, g_psum);
    cudaGetSymbolAddress((void**)&gb, g_g);
    cudaGetSymbolAddress((void**)&h1, g_h1);
    cudaGetSymbolAddress((void**)&h2, g_h2);
    cudaGetSymbolAddress((void**)&XCh, g_XCh);
    cudaGetSymbolAddress((void**)&XCl, g_XCl);
    cudaGetSymbolAddress((void**)&W5h, g_W5h);
    cudaGetSymbolAddress((void**)&W5l, g_W5l);
    cudaGetSymbolAddress((void**)&Wh, g_Wh);
    cudaGetSymbolAddress((void**)&Wl, g_Wl);

    cudaFuncSetAttribute(gemm_mma, cudaFuncAttributeMaxDynamicSharedMemorySize, GSM_TOTAL);
    cudaFuncSetAttribute(topk_kernel, cudaFuncAttributeMaxDynamicSharedMemorySize, TOPK_SMEM);

    const int TOTAL = BSZ * NPTS;  // 16384
    const int WOFF[3] = {0, 8192, 24576};

    // ---------- hoisted weight prep ----------
    make_weff_split<<<(2 * 64 * 64 + 255) / 256, 256>>>(w2, 64, 64, Wh + WOFF[0], Wl + WOFF[0]);
    make_weff_split<<<(2 * 128 * 64 + 255) / 256, 256>>>(w3, 128, 64, Wh + WOFF[1], Wl + WOFF[1]);
    make_weff_split<<<(2 * 256 * 128 + 255) / 256, 256>>>(w4, 256, 128, Wh + WOFF[2], Wl + WOFF[2]);
    d2split_kernel<<<1024 / 8, 256>>>(w5, 512, 512, 1024, W5h, W5l, nullptr);

    // ---------- layer 1 (exact fp32; K=3); gather emits x1 hi/lo + d2(x1) ----------
    l1yz_d2<<<(int)(((long)TOTAL * 128) / 256), 256>>>(x, w1, YZ, d2);
    gemm_abT<<<dim3(NPTS / BN, NPTS / BM, BSZ), 256>>>(
        x, 3, (long)NPTS * 3, x, 3, (long)NPTS * 3,
        S, NPTS, (long)NPTS * NPTS, NPTS, NPTS, 3, d2, NPTS, 1);
    topk_kernel<<<TOTAL / 8, 256, TOPK_SMEM>>>(S, idx);
    gather_max<<<dim3(NPTS, BSZ), 64>>>(YZ, 128, idx, bn1, XCh, XCl, 0, d2, 64);

    // ---------- layers 2-4 (HMMA fp16-split; features read from XCh/XCl, ld 512) ----------
    struct L { int coff, C, O, outoff, woff, yznp; const float* bn; int emitd2; };
    L Ls[3] = { {0, 64, 64, 64, WOFF[0], 3, bn2, 1},
                {64, 64, 128, 128, WOFF[1], 3, bn3, 1},
                {128, 128, 256, 256, WOFF[2], 2, bn4, 0} };
    for (int l = 0; l < 3; l++) {
        const L& c = Ls[l];
        gemm_mma<<<dim3(16, 16, BSZ), 256, GSM_TOTAL>>>(
            XCh + c.coff, XCl + c.coff, 512, (long)NPTS * 512,
            XCh + c.coff, XCl + c.coff, 512, (long)NPTS * 512,
            S, NPTS, (long)NPTS * NPTS, c.C, d2, nullptr, NPTS, 1, 3, nullptr, nullptr);
        topk_kernel<<<TOTAL / 8, 256, TOPK_SMEM>>>(S, idx);
        gemm_mma<<<dim3(2 * c.O / 128, TOTAL / 128, 1), 256, GSM_TOTAL>>>(
            XCh + c.coff, XCl + c.coff, 512, 0,
            Wh + c.woff, Wl + c.woff, c.C, 0,
            YZ, 2 * c.O, 0, c.C, nullptr, nullptr, 2 * c.O, 0, c.yznp, nullptr, nullptr);
        gather_max<<<dim3(NPTS, BSZ), c.O>>>(YZ, 2 * c.O, idx, c.bn,
                                             XCh, XCl, c.outoff, c.emitd2 ? d2 : nullptr, c.O);
    }

    // ---------- x5 GEMM with fused pool partials (npass=2) ----------
    gemm_mma<<<dim3(8, TOTAL / 128, 1), 256, GSM_TOTAL>>>(
        XCh, XCl, 512, 0, W5h, W5l, 512, 0,
        nullptr, 1024, 0, 512, nullptr, bn5, 1024, 3, 2, pmax, psum);
    pool_reduce<<<dim3(4, BSZ), 256>>>(pmax, psum, gb);

    // ---------- FC stack ----------
    fc_kernel<<<dim3(512, BSZ), 128>>>(gb, 2048, wl1, nullptr, bn6, 1, h1, 512);
    fc_kernel<<<dim3(256, BSZ), 128>>>(h1, 512, wl2, bl2, bn7, 1, h2, 256);
    fc_kernel<<<dim3(40, BSZ), 128>>>(h2, 256, wl3, bl3, nullptr, 0, (float*)d_out, 40);
}

// round 15
// speedup vs baseline: 1.0335x; 1.0335x over previous
#include <cuda_runtime.h>
#include <cuda_fp16.h>
#include <cstdint>
#include <math.h>

#define BSZ 8
#define NPTS 2048
#define KNN 20
#define EPS 1e-5f
#define SLOPE 0.2f

// ---------------- scratch (device globals) ----------------
__device__ float g_S[(long)BSZ * NPTS * NPTS];   // layers 2-4 gram scores only now
__device__ float g_d2[BSZ * NPTS];
__device__ int   g_idx[BSZ * NPTS * KNN];
__device__ float g_YZ[(long)BSZ * NPTS * 512];
__device__ float g_pmax[128 * 1024];
__device__ float g_psum[128 * 1024];
__device__ float g_g[BSZ * 2048];
__device__ float g_h1[BSZ * 512];
__device__ float g_h2[BSZ * 256];
// unified feature hi/lo (ld = 512): columns 0..511 = [x1 | x2 | x3 | x4]
__device__ __align__(16) unsigned short g_XCh[(long)BSZ * NPTS * 512];
__device__ __align__(16) unsigned short g_XCl[(long)BSZ * NPTS * 512];
__device__ __align__(16) unsigned short g_W5h[1024 * 512];
__device__ __align__(16) unsigned short g_W5l[1024 * 512];
__device__ __align__(16) unsigned short g_Wh[90112];
__device__ __align__(16) unsigned short g_Wl[90112];

__device__ __forceinline__ uint32_t smem_u32(const void* p) {
    uint32_t a;
    asm("{ .reg .u64 t; cvta.to.shared.u64 t, %1; cvt.u32.u64 %0, t; }" : "=r"(a) : "l"(p));
    return a;
}

#define LDSM4(f, addr) \
    asm volatile("ldmatrix.sync.aligned.m8n8.x4.shared.b16 {%0,%1,%2,%3}, [%4];" \
                 : "=r"((f)[0]), "=r"((f)[1]), "=r"((f)[2]), "=r"((f)[3]) : "r"(addr))

#define MMA16816(c, a, b0, b1) \
    asm volatile("mma.sync.aligned.m16n8k16.row.col.f32.f16.f16.f32 " \
                 "{%0,%1,%2,%3}, {%4,%5,%6,%7}, {%8,%9}, {%0,%1,%2,%3};" \
                 : "+f"((c)[0]), "+f"((c)[1]), "+f"((c)[2]), "+f"((c)[3]) \
                 : "r"((a)[0]), "r"((a)[1]), "r"((a)[2]), "r"((a)[3]), "r"(b0), "r"(b1))

#define CPA16(dst, src) \
    asm volatile("cp.async.ca.shared.global [%0], [%1], 16;" :: "r"(dst), "l"(src))
#define CPA_COMMIT() asm volatile("cp.async.commit_group;" ::: "memory")
#define CPA_WAIT0() asm volatile("cp.async.wait_group 0;" ::: "memory")
#define CPA_WAIT1() asm volatile("cp.async.wait_group 1;" ::: "memory")

// ======================= HMMA split-fp16 GEMM (double-buffered cp.async) ===========
// C = A(MxK, row-stride ldA) * B(NxK, row-stride ldB)^T, fp16 hi/lo.
// npass: 2 = hh+hl; 3 = hh+hl+lh.
// mode 0: raw; 1: 2v-d2[col]; 2: bn+leakyrelu; 3: bn+act + pooled partials.
#define GSM_BUF 8192
#define GSM_TOTAL (2 * 4 * GSM_BUF + 2048)

__global__ __launch_bounds__(256) void gemm_mma(
        const unsigned short* __restrict__ Ah0, const unsigned short* __restrict__ Al0,
        int ldA, long bsA,
        const unsigned short* __restrict__ Bh0, const unsigned short* __restrict__ Bl0,
        int ldB, long bsB,
        float* __restrict__ Cm, int ldc, long bsC,
        int K, const float* __restrict__ d2, const float* __restrict__ bnp,
        int Nn, int mode, int npass,
        float* __restrict__ pmax, float* __restrict__ psum) {
    extern __shared__ __align__(16) char dyn[];
    float* redm = (float*)(dyn + 2 * 4 * GSM_BUF);
    float* reds = redm + 256;

    int tid = threadIdx.x, wid = tid >> 5, lane = tid & 31;
    int bm = blockIdx.y * 128, bn = blockIdx.x * 128, z = blockIdx.z;

    const unsigned short* Ah = Ah0 + (long)z * bsA;
    const unsigned short* Al = Al0 + (long)z * bsA;
    const unsigned short* Bh = Bh0 + (long)z * bsB;
    const unsigned short* Bl = Bl0 + (long)z * bsB;

    int wm = (wid >> 2) * 64, wn = (wid & 3) * 32;
    int a_r = lane & 15, a_kh = lane >> 4;
    int b_n = (lane & 7) + ((lane >> 4) << 3), b_kh = (lane >> 3) & 1;

    uint32_t ub = smem_u32(dyn);

    int r0 = tid >> 2, ci0 = tid & 3;
    int r1 = (tid + 256) >> 2, ci1 = (tid + 256) & 3;
    int ph0 = r0 * 64 + ((ci0 ^ ((r0 >> 1) & 3)) * 16);
    int ph1 = r1 * 64 + ((ci1 ^ ((r1 >> 1) & 3)) * 16);

    int nch = K >> 5;

#define LOAD_CHUNK(bufi, k0_) do { \
    uint32_t o = ub + (bufi) * 4 * GSM_BUF; \
    long gA0 = (long)(bm + r0) * ldA + (k0_) + ci0 * 8; \
    long gA1 = (long)(bm + r1) * ldA + (k0_) + ci1 * 8; \
    long gB0 = (long)(bn + r0) * ldB + (k0_) + ci0 * 8; \
    long gB1 = (long)(bn + r1) * ldB + (k0_) + ci1 * 8; \
    CPA16(o + ph0, Ah + gA0);                 CPA16(o + ph1, Ah + gA1); \
    CPA16(o + 2 * GSM_BUF + ph0, Bh + gB0);   CPA16(o + 2 * GSM_BUF + ph1, Bh + gB1); \
    CPA16(o + GSM_BUF + ph0, Al + gA0);       CPA16(o + GSM_BUF + ph1, Al + gA1); \
    CPA16(o + 3 * GSM_BUF + ph0, Bl + gB0);   CPA16(o + 3 * GSM_BUF + ph1, Bl + gB1); \
    CPA_COMMIT(); \
} while (0)

    float acc[4][4][4] = {};

    LOAD_CHUNK(0, 0);
    for (int ch = 0; ch < nch; ch++) {
        if (ch + 1 < nch) {
            LOAD_CHUNK((ch + 1) & 1, (ch + 1) << 5);
            CPA_WAIT1();
        } else {
            CPA_WAIT0();
        }
        __syncthreads();
        uint32_t o = ub + (ch & 1) * 4 * GSM_BUF;
        uint32_t sAh = o, sAl = o + GSM_BUF, sBh = o + 2 * GSM_BUF, sBl = o + 3 * GSM_BUF;
#pragma unroll
        for (int s = 0; s < 2; s++) {
            uint32_t af[4][4], bfh[2][4], bfl[2][4];
#pragma unroll
            for (int mt = 0; mt < 4; mt++) {
                int row = wm + mt * 16 + a_r;
                int chh = 2 * s + a_kh;
                LDSM4(af[mt], sAh + row * 64 + ((chh ^ ((row >> 1) & 3)) * 16));
            }
#pragma unroll
            for (int g = 0; g < 2; g++) {
                int row = wn + g * 16 + b_n;
                int chh = 2 * s + b_kh;
                LDSM4(bfh[g], sBh + row * 64 + ((chh ^ ((row >> 1) & 3)) * 16));
            }
#pragma unroll
            for (int mt = 0; mt < 4; mt++)
#pragma unroll
                for (int nt = 0; nt < 4; nt++)
                    MMA16816(acc[mt][nt], af[mt], bfh[nt >> 1][(nt & 1) * 2], bfh[nt >> 1][(nt & 1) * 2 + 1]);
#pragma unroll
            for (int g = 0; g < 2; g++) {
                int row = wn + g * 16 + b_n;
                int chh = 2 * s + b_kh;
                LDSM4(bfl[g], sBl + row * 64 + ((chh ^ ((row >> 1) & 3)) * 16));
            }
#pragma unroll
            for (int mt = 0; mt < 4; mt++)
#pragma unroll
                for (int nt = 0; nt < 4; nt++)
                    MMA16816(acc[mt][nt], af[mt], bfl[nt >> 1][(nt & 1) * 2], bfl[nt >> 1][(nt & 1) * 2 + 1]);
            if (npass > 2) {
#pragma unroll
                for (int mt = 0; mt < 4; mt++) {
                    int row = wm + mt * 16 + a_r;
                    int chh = 2 * s + a_kh;
                    LDSM4(af[mt], sAl + row * 64 + ((chh ^ ((row >> 1) & 3)) * 16));
                }
#pragma unroll
                for (int mt = 0; mt < 4; mt++)
#pragma unroll
                    for (int nt = 0; nt < 4; nt++)
                        MMA16816(acc[mt][nt], af[mt], bfh[nt >> 1][(nt & 1) * 2], bfh[nt >> 1][(nt & 1) * 2 + 1]);
            }
        }
        __syncthreads();
    }

    if (mode == 3) {
        float cmax[8], csum[8];
#pragma unroll
        for (int q = 0; q < 8; q++) { cmax[q] = -INFINITY; csum[q] = 0.f; }
#pragma unroll
        for (int mt = 0; mt < 4; mt++)
#pragma unroll
            for (int h = 0; h < 2; h++)
#pragma unroll
                for (int nt = 0; nt < 4; nt++)
#pragma unroll
                    for (int j = 0; j < 2; j++) {
                        int col = bn + wn + nt * 8 + (lane & 3) * 2 + j;
                        float v = acc[mt][nt][h * 2 + j];
                        float gg = bnp[col], be = bnp[Nn + col];
                        float mm = bnp[2 * Nn + col], vv = bnp[3 * Nn + col];
                        v = (v - mm) * (gg * rsqrtf(vv + EPS)) + be;
                        v = v > 0.f ? v : SLOPE * v;
                        int q = nt * 2 + j;
                        cmax[q] = fmaxf(cmax[q], v);
                        csum[q] += v;
                    }
#pragma unroll
        for (int q = 0; q < 8; q++) {
#pragma unroll
            for (int off = 4; off < 32; off <<= 1) {
                cmax[q] = fmaxf(cmax[q], __shfl_xor_sync(0xffffffffu, cmax[q], off));
                csum[q] += __shfl_xor_sync(0xffffffffu, csum[q], off);
            }
        }
        if ((lane >> 2) == 0) {
            int g = wid >> 2;
#pragma unroll
            for (int nt = 0; nt < 4; nt++)
#pragma unroll
                for (int j = 0; j < 2; j++) {
                    int cl = wn + nt * 8 + (lane & 3) * 2 + j;
                    redm[g * 128 + cl] = cmax[nt * 2 + j];
                    reds[g * 128 + cl] = csum[nt * 2 + j];
                }
        }
        __syncthreads();
        if (tid < 128) {
            pmax[(long)blockIdx.y * 1024 + bn + tid] = fmaxf(redm[tid], redm[128 + tid]);
            psum[(long)blockIdx.y * 1024 + bn + tid] = reds[tid] + reds[128 + tid];
        }
        return;
    }

    float* Cb = Cm + (long)z * bsC;
#pragma unroll
    for (int mt = 0; mt < 4; mt++) {
        int rr = bm + wm + mt * 16 + (lane >> 2);
#pragma unroll
        for (int h = 0; h < 2; h++) {
            int row = rr + h * 8;
#pragma unroll
            for (int nt = 0; nt < 4; nt++) {
                int col = bn + wn + nt * 8 + (lane & 3) * 2;
                float v0 = acc[mt][nt][h * 2];
                float v1 = acc[mt][nt][h * 2 + 1];
                if (mode == 1) {
                    const float* dd = d2 + (long)z * NPTS;
                    v0 = 2.f * v0 - dd[col];
                    v1 = 2.f * v1 - dd[col + 1];
                } else if (mode == 2) {
                    float gg = bnp[col], be = bnp[Nn + col];
                    float mm = bnp[2 * Nn + col], vv = bnp[3 * Nn + col];
                    v0 = (v0 - mm) * (gg * rsqrtf(vv + EPS)) + be;
                    v0 = v0 > 0.f ? v0 : SLOPE * v0;
                    gg = bnp[col + 1]; be = bnp[Nn + col + 1];
                    mm = bnp[2 * Nn + col + 1]; vv = bnp[3 * Nn + col + 1];
                    v1 = (v1 - mm) * (gg * rsqrtf(vv + EPS)) + be;
                    v1 = v1 > 0.f ? v1 : SLOPE * v1;
                }
                *(float2*)&Cb[(long)row * ldc + col] = make_float2(v0, v1);
            }
        }
    }
}

// ======================= pool reduce =======================
__global__ void pool_reduce(const float* __restrict__ pmax, const float* __restrict__ psum,
                            float* __restrict__ gb) {
    int c = blockIdx.x * 256 + threadIdx.x;
    int b = blockIdx.y;
    float m = -INFINITY, s = 0.f;
#pragma unroll
    for (int i = 0; i < 16; i++) {
        int by = b * 16 + i;
        m = fmaxf(m, pmax[(long)by * 1024 + c]);
        s += psum[(long)by * 1024 + c];
    }
    gb[b * 2048 + c] = m;
    gb[b * 2048 + 1024 + c] = s * (1.0f / NPTS);
}

// ======================= fused layer-1 YZ (K=3) =======================
__global__ __launch_bounds__(256) void l1yz_d2(
        const float* __restrict__ x, const float* __restrict__ w1,
        float* __restrict__ YZ) {
    __shared__ float wf[128][3];
    int tid = threadIdx.x;
    if (tid < 128) {
        int o = tid & 63;
        if (tid < 64) {
            wf[tid][0] = w1[o * 6 + 0];
            wf[tid][1] = w1[o * 6 + 1];
            wf[tid][2] = w1[o * 6 + 2];
        } else {
            wf[tid][0] = w1[o * 6 + 3] - w1[o * 6 + 0];
            wf[tid][1] = w1[o * 6 + 4] - w1[o * 6 + 1];
            wf[tid][2] = w1[o * 6 + 5] - w1[o * 6 + 2];
        }
    }
    __syncthreads();
    long i = (long)blockIdx.x * 256 + tid;
    int n = (int)(i >> 7), o = (int)(i & 127);
    float x0 = x[n * 3], x1 = x[n * 3 + 1], x2 = x[n * 3 + 2];
    YZ[i] = x0 * wf[o][0] + x1 * wf[o][1] + x2 * wf[o][2];
}

// ======================= fused layer-1 KNN: scores (K=3) + top-20 ===============
// One block = 8 rows of one batch; block caches all 2048 points' xyz in smem,
// computes scores inline, then runs the group-cached selection.
#define TOPK_L1_SMEM ((8 * 2048 + 3 * 2048) * 4)
__global__ __launch_bounds__(256) void topk_l1(const float* __restrict__ xg,
                                               int* __restrict__ idxo) {
    extern __shared__ float sm[];
    float* sv_all = sm;                  // 8 * 2048 scores
    float* cx = sm + 8 * 2048;           // 2048
    float* cy = cx + 2048;
    float* cz = cy + 2048;
    int warp = threadIdx.x >> 5, lane = threadIdx.x & 31;
    int b = blockIdx.y;
    int row = blockIdx.x * 8 + warp;
    const float* xb = xg + (long)b * NPTS * 3;
    for (int j = threadIdx.x; j < NPTS; j += 256) {
        cx[j] = xb[j * 3];
        cy[j] = xb[j * 3 + 1];
        cz[j] = xb[j * 3 + 2];
    }
    __syncthreads();
    float* sv = sv_all + warp * 2048;
    float r0 = cx[row], r1 = cy[row], r2 = cz[row];

    float gmax[8];
    int gj[8];
#pragma unroll
    for (int g = 0; g < 8; g++) {
        float bm = -INFINITY;
        int bj = g * 8;
#pragma unroll
        for (int e = 0; e < 8; e++) {
            int j = g * 8 + e;
            int col = j * 32 + lane;
            float c0 = cx[col], c1 = cy[col], c2 = cz[col];
            float dot = fmaf(r2, c2, fmaf(r1, c1, r0 * c0));
            float dd = fmaf(c2, c2, fmaf(c1, c1, c0 * c0));
            float v = 2.f * dot - dd;
            sv[col] = v;
            if (v > bm) { bm = v; bj = j; }
        }
        gmax[g] = bm; gj[g] = bj;
    }

    for (int it = 0; it < KNN; it++) {
        float best = gmax[0];
        int bj = gj[0];
#pragma unroll
        for (int g = 1; g < 8; g++)
            if (gmax[g] > best) { best = gmax[g]; bj = gj[g]; }
        int bidx = bj * 32 + lane;
        float wb = best;
        int wi = bidx;
#pragma unroll
        for (int o = 16; o; o >>= 1) {
            float ov = __shfl_down_sync(0xffffffffu, wb, o);
            int oi = __shfl_down_sync(0xffffffffu, wi, o);
            if (ov > wb || (ov == wb && oi < wi)) { wb = ov; wi = oi; }
        }
        wi = __shfl_sync(0xffffffffu, wi, 0);
        if (lane == 0) idxo[((long)b * NPTS + row) * KNN + it] = wi;
        if ((wi & 31) == lane) {
            int j = wi >> 5;
            int g = j >> 3;
            sv[j * 32 + lane] = -INFINITY;
            float bm = -INFINITY;
            int bjn = g * 8;
            for (int e = 0; e < 8; e++) {
                int jj = g * 8 + e;
                float v = sv[jj * 32 + lane];
                if (v > bm) { bm = v; bjn = jj; }
            }
#pragma unroll
            for (int gg = 0; gg < 8; gg++)
                if (gg == g) { gmax[gg] = bm; gj[gg] = bjn; }
        }
    }
}

// ======================= d2 + split (weights only) =======================
__global__ void d2split_kernel(const float* __restrict__ src, int ld, int C, int rows,
                               unsigned short* __restrict__ hi, unsigned short* __restrict__ lo,
                               float* __restrict__ d2) {
    int row = blockIdx.x * 8 + (threadIdx.x >> 5);
    int lane = threadIdx.x & 31;
    if (row >= rows) return;
    const float* xr = src + (long)row * ld;
    float s = 0.f;
    for (int c = lane; c < C; c += 32) {
        float v = xr[c];
        s += v * v;
        __half h = __float2half_rn(v);
        __half l = __float2half_rn(v - __half2float(h));
        hi[(long)row * C + c] = *(unsigned short*)&h;
        lo[(long)row * C + c] = *(unsigned short*)&l;
    }
    if (d2) {
#pragma unroll
        for (int o = 16; o; o >>= 1) s += __shfl_xor_sync(0xffffffffu, s, o);
        if (lane == 0) d2[row] = s;
    }
}

__global__ void make_weff_split(const float* __restrict__ w, int O, int C,
                                unsigned short* __restrict__ hi, unsigned short* __restrict__ lo) {
    int i = blockIdx.x * blockDim.x + threadIdx.x;
    if (i >= 2 * O * C) return;
    int row = i / C, c = i % C;
    float v;
    if (row < O) v = w[row * 2 * C + c];
    else { int o = row - O; v = w[o * 2 * C + C + c] - w[o * 2 * C + c]; }
    __half h = __float2half_rn(v);
    __half l = __float2half_rn(v - __half2float(h));
    hi[i] = *(unsigned short*)&h;
    lo[i] = *(unsigned short*)&l;
}

// ---------------- top-k (layers 2-4): warp/row, smem values + group-max cache ----
#define TOPK_SMEM (8 * 2048 * 4)
__global__ __launch_bounds__(256) void topk_kernel(const float* __restrict__ S,
                                                   int* __restrict__ idxo) {
    extern __shared__ float sv_all[];
    int warp = threadIdx.x >> 5, lane = threadIdx.x & 31;
    int row = blockIdx.x * 8 + warp;
    float* sv = sv_all + warp * 2048;
    const float* s = S + (long)row * NPTS;

    float gmax[8];
    int gj[8];
#pragma unroll
    for (int g = 0; g < 8; g++) {
        float bm = -INFINITY;
        int bj = g * 8;
#pragma unroll
        for (int e = 0; e < 8; e++) {
            int j = g * 8 + e;
            float v = s[j * 32 + lane];
            sv[j * 32 + lane] = v;
            if (v > bm) { bm = v; bj = j; }
        }
        gmax[g] = bm; gj[g] = bj;
    }

    for (int it = 0; it < KNN; it++) {
        float best = gmax[0];
        int bj = gj[0];
#pragma unroll
        for (int g = 1; g < 8; g++)
            if (gmax[g] > best) { best = gmax[g]; bj = gj[g]; }
        int bidx = bj * 32 + lane;
        float wb = best;
        int wi = bidx;
#pragma unroll
        for (int o = 16; o; o >>= 1) {
            float ov = __shfl_down_sync(0xffffffffu, wb, o);
            int oi = __shfl_down_sync(0xffffffffu, wi, o);
            if (ov > wb || (ov == wb && oi < wi)) { wb = ov; wi = oi; }
        }
        wi = __shfl_sync(0xffffffffu, wi, 0);
        if (lane == 0) idxo[(long)row * KNN + it] = wi;
        if ((wi & 31) == lane) {
            int j = wi >> 5;
            int g = j >> 3;
            sv[j * 32 + lane] = -INFINITY;
            float bm = -INFINITY;
            int bjn = g * 8;
            for (int e = 0; e < 8; e++) {
                int jj = g * 8 + e;
                float v = sv[jj * 32 + lane];
                if (v > bm) { bm = v; bjn = jj; }
            }
#pragma unroll
            for (int gg = 0; gg < 8; gg++)
                if (gg == g) { gmax[gg] = bm; gj[gg] = bjn; }
        }
    }
}

// ---------------- gather + max + bn + act + fp16 split + d2 emit ----------------
__global__ void gather_max(const float* __restrict__ YZ, int twoO,
                           const int* __restrict__ idxi,
                           const float* __restrict__ bnp,
                           unsigned short* __restrict__ hi, unsigned short* __restrict__ lo,
                           int outoff, float* __restrict__ d2, int O) {
    int n = blockIdx.x, b = blockIdx.y, o = threadIdx.x;
    __shared__ int si[KNN];
    __shared__ float red[8];
    if (o < KNN) si[o] = idxi[((long)b * NPTS + n) * KNN + o];
    __syncthreads();
    const float* Yb = YZ + (long)b * NPTS * twoO;
    float m = -INFINITY;
#pragma unroll 4
    for (int k = 0; k < KNN; k++) m = fmaxf(m, Yb[(long)si[k] * twoO + o]);
    float z = Yb[(long)n * twoO + O + o];
    float t = m + z;
    float gg = bnp[o], be = bnp[O + o], mm = bnp[2 * O + o], vv = bnp[3 * O + o];
    float v = (t - mm) * (gg * rsqrtf(vv + EPS)) + be;
    v = v > 0.f ? v : SLOPE * v;
    long base = ((long)b * NPTS + n) * 512 + outoff + o;
    __half h = __float2half_rn(v);
    __half l2 = __float2half_rn(v - __half2float(h));
    hi[base] = *(unsigned short*)&h;
    lo[base] = *(unsigned short*)&l2;
    if (d2) {
        float s = v * v;
#pragma unroll
        for (int off = 16; off; off >>= 1) s += __shfl_down_sync(0xffffffffu, s, off);
        if ((o & 31) == 0) red[o >> 5] = s;
        __syncthreads();
        if (o == 0) {
            float tot = 0.f;
            for (int w = 0; w < (O >> 5); w++) tot += red[w];
            d2[b * NPTS + n] = tot;
        }
    }
}

// ---------------- small FC ----------------
__global__ void fc_kernel(const float* __restrict__ in, int K,
                          const float* __restrict__ W,
                          const float* __restrict__ bias,
                          const float* __restrict__ bnp, int useAct,
                          float* __restrict__ out, int O) {
    int o = blockIdx.x, b = blockIdx.y, t = threadIdx.x;
    const float* xr = in + (long)b * K;
    const float* wr = W + (long)o * K;
    float s = 0.f;
    for (int k = t; k < K; k += 128) s += xr[k] * wr[k];
    __shared__ float red[4];
#pragma unroll
    for (int off = 16; off; off >>= 1) s += __shfl_down_sync(0xffffffffu, s, off);
    if ((t & 31) == 0) red[t >> 5] = s;
    __syncthreads();
    if (t == 0) {
        float tot = red[0] + red[1] + red[2] + red[3];
        if (bias) tot += bias[o];
        if (bnp) {
            float gg = bnp[o], be = bnp[O + o], mm = bnp[2 * O + o], vv = bnp[3 * O + o];
            tot = (tot - mm) * (gg * rsqrtf(vv + EPS)) + be;
        }
        if (useAct) tot = tot > 0.f ? tot : SLOPE * tot;
        out[(long)b * O + o] = tot;
    }
}

extern "C" void kernel_launch(void* const* d_in, const int* in_sizes, int n_in,
                              void* d_out, int out_size) {
    const float* x   = (const float*)d_in[0];
    const float* w1  = (const float*)d_in[2];
    const float* w2  = (const float*)d_in[3];
    const float* w3  = (const float*)d_in[4];
    const float* w4  = (const float*)d_in[5];
    const float* w5  = (const float*)d_in[6];
    const float* wl1 = (const float*)d_in[7];
    const float* wl2 = (const float*)d_in[8];
    const float* bl2 = (const float*)d_in[9];
    const float* wl3 = (const float*)d_in[10];
    const float* bl3 = (const float*)d_in[11];
    const float* bn1 = (const float*)d_in[12];
    const float* bn2 = (const float*)d_in[13];
    const float* bn3 = (const float*)d_in[14];
    const float* bn4 = (const float*)d_in[15];
    const float* bn5 = (const float*)d_in[16];
    const float* bn6 = (const float*)d_in[17];
    const float* bn7 = (const float*)d_in[18];

    float *S, *d2, *YZ, *pmax, *psum, *gb, *h1, *h2;
    int* idx;
    unsigned short *XCh, *XCl, *W5h, *W5l, *Wh, *Wl;
    cudaGetSymbolAddress((void**)&S, g_S);
    cudaGetSymbolAddress((void**)&d2, g_d2);
    cudaGetSymbolAddress((void**)&idx, g_idx);
    cudaGetSymbolAddress((void**)&YZ, g_YZ);
    cudaGetSymbolAddress((void**)&pmax, g_pmax);
    cudaGetSymbolAddress((void**)&psum, g_psum);
    cudaGetSymbolAddress((void**)&gb, g_g);
    cudaGetSymbolAddress((void**)&h1, g_h1);
    cudaGetSymbolAddress((void**)&h2, g_h2);
    cudaGetSymbolAddress((void**)&XCh, g_XCh);
    cudaGetSymbolAddress((void**)&XCl, g_XCl);
    cudaGetSymbolAddress((void**)&W5h, g_W5h);
    cudaGetSymbolAddress((void**)&W5l, g_W5l);
    cudaGetSymbolAddress((void**)&Wh, g_Wh);
    cudaGetSymbolAddress((void**)&Wl, g_Wl);

    cudaFuncSetAttribute(gemm_mma, cudaFuncAttributeMaxDynamicSharedMemorySize, GSM_TOTAL);
    cudaFuncSetAttribute(topk_kernel, cudaFuncAttributeMaxDynamicSharedMemorySize, TOPK_SMEM);
    cudaFuncSetAttribute(topk_l1, cudaFuncAttributeMaxDynamicSharedMemorySize, TOPK_L1_SMEM);

    const int TOTAL = BSZ * NPTS;  // 16384
    const int WOFF[3] = {0, 8192, 24576};

    // ---------- hoisted weight prep ----------
    make_weff_split<<<(2 * 64 * 64 + 255) / 256, 256>>>(w2, 64, 64, Wh + WOFF[0], Wl + WOFF[0]);
    make_weff_split<<<(2 * 128 * 64 + 255) / 256, 256>>>(w3, 128, 64, Wh + WOFF[1], Wl + WOFF[1]);
    make_weff_split<<<(2 * 256 * 128 + 255) / 256, 256>>>(w4, 256, 128, Wh + WOFF[2], Wl + WOFF[2]);
    d2split_kernel<<<1024 / 8, 256>>>(w5, 512, 512, 1024, W5h, W5l, nullptr);

    // ---------- layer 1 (exact fp32; K=3): fused score+topk, no S matrix ----------
    l1yz_d2<<<(int)(((long)TOTAL * 128) / 256), 256>>>(x, w1, YZ);
    topk_l1<<<dim3(NPTS / 8, BSZ), 256, TOPK_L1_SMEM>>>(x, idx);
    gather_max<<<dim3(NPTS, BSZ), 64>>>(YZ, 128, idx, bn1, XCh, XCl, 0, d2, 64);

    // ---------- layers 2-4 (HMMA fp16-split; features read from XCh/XCl, ld 512) ----------
    struct L { int coff, C, O, outoff, woff, yznp; const float* bn; int emitd2; };
    L Ls[3] = { {0, 64, 64, 64, WOFF[0], 3, bn2, 1},
                {64, 64, 128, 128, WOFF[1], 3, bn3, 1},
                {128, 128, 256, 256, WOFF[2], 2, bn4, 0} };
    for (int l = 0; l < 3; l++) {
        const L& c = Ls[l];
        gemm_mma<<<dim3(16, 16, BSZ), 256, GSM_TOTAL>>>(
            XCh + c.coff, XCl + c.coff, 512, (long)NPTS * 512,
            XCh + c.coff, XCl + c.coff, 512, (long)NPTS * 512,
            S, NPTS, (long)NPTS * NPTS, c.C, d2, nullptr, NPTS, 1, 3, nullptr, nullptr);
        topk_kernel<<<TOTAL / 8, 256, TOPK_SMEM>>>(S, idx);
        gemm_mma<<<dim3(2 * c.O / 128, TOTAL / 128, 1), 256, GSM_TOTAL>>>(
            XCh + c.coff, XCl + c.coff, 512, 0,
            Wh + c.woff, Wl + c.woff, c.C, 0,
            YZ, 2 * c.O, 0, c.C, nullptr, nullptr, 2 * c.O, 0, c.yznp, nullptr, nullptr);
        gather_max<<<dim3(NPTS, BSZ), c.O>>>(YZ, 2 * c.O, idx, c.bn,
                                             XCh, XCl, c.outoff, c.emitd2 ? d2 : nullptr, c.O);
    }

    // ---------- x5 GEMM with fused pool partials (npass=2) ----------
    gemm_mma<<<dim3(8, TOTAL / 128, 1), 256, GSM_TOTAL>>>(
        XCh, XCl, 512, 0, W5h, W5l, 512, 0,
        nullptr, 1024, 0, 512, nullptr, bn5, 1024, 3, 2, pmax, psum);
    pool_reduce<<<dim3(4, BSZ), 256>>>(pmax, psum, gb);

    // ---------- FC stack ----------
    fc_kernel<<<dim3(512, BSZ), 128>>>(gb, 2048, wl1, nullptr, bn6, 1, h1, 512);
    fc_kernel<<<dim3(256, BSZ), 128>>>(h1, 512, wl2, bl2, bn7, 1, h2, 256);
    fc_kernel<<<dim3(40, BSZ), 128>>>(h2, 256, wl3, bl3, nullptr, 0, (float*)d_out, 40);
}

// round 16
// speedup vs baseline: 1.0542x; 1.0201x over previous
#include <cuda_runtime.h>
#include <cuda_fp16.h>
#include <cstdint>
#include <math.h>

#define BSZ 8
#define NPTS 2048
#define KNN 20
#define EPS 1e-5f
#define SLOPE 0.2f

// ---------------- scratch (device globals) ----------------
__device__ float g_S[(long)BSZ * NPTS * NPTS];
__device__ float g_d2[BSZ * NPTS];
__device__ int   g_idx[BSZ * NPTS * KNN];
__device__ float g_YZ[(long)BSZ * NPTS * 512];
__device__ float g_pmax[128 * 1024];
__device__ float g_psum[128 * 1024];
__device__ float g_g[BSZ * 2048];
__device__ float g_h1[BSZ * 512];
__device__ float g_h2[BSZ * 256];
__device__ __align__(16) unsigned short g_XCh[(long)BSZ * NPTS * 512];
__device__ __align__(16) unsigned short g_XCl[(long)BSZ * NPTS * 512];
__device__ __align__(16) unsigned short g_W5h[1024 * 512];
__device__ __align__(16) unsigned short g_W5l[1024 * 512];
__device__ __align__(16) unsigned short g_Wh[90112];
__device__ __align__(16) unsigned short g_Wl[90112];

__device__ __forceinline__ uint32_t smem_u32(const void* p) {
    uint32_t a;
    asm("{ .reg .u64 t; cvta.to.shared.u64 t, %1; cvt.u32.u64 %0, t; }" : "=r"(a) : "l"(p));
    return a;
}

#define LDSM4(f, addr) \
    asm volatile("ldmatrix.sync.aligned.m8n8.x4.shared.b16 {%0,%1,%2,%3}, [%4];" \
                 : "=r"((f)[0]), "=r"((f)[1]), "=r"((f)[2]), "=r"((f)[3]) : "r"(addr))

#define MMA16816(c, a, b0, b1) \
    asm volatile("mma.sync.aligned.m16n8k16.row.col.f32.f16.f16.f32 " \
                 "{%0,%1,%2,%3}, {%4,%5,%6,%7}, {%8,%9}, {%0,%1,%2,%3};" \
                 : "+f"((c)[0]), "+f"((c)[1]), "+f"((c)[2]), "+f"((c)[3]) \
                 : "r"((a)[0]), "r"((a)[1]), "r"((a)[2]), "r"((a)[3]), "r"(b0), "r"(b1))

#define CPA16(dst, src) \
    asm volatile("cp.async.ca.shared.global [%0], [%1], 16;" :: "r"(dst), "l"(src))
#define CPA_COMMIT() asm volatile("cp.async.commit_group;" ::: "memory")
#define CPA_WAIT0() asm volatile("cp.async.wait_group 0;" ::: "memory")
#define CPA_WAIT1() asm volatile("cp.async.wait_group 1;" ::: "memory")

// ======================= HMMA split-fp16 GEMM (double-buffered cp.async) ===========
#define GSM_BUF 8192
#define GSM_TOTAL (2 * 4 * GSM_BUF + 2048)

__global__ __launch_bounds__(256) void gemm_mma(
        const unsigned short* __restrict__ Ah0, const unsigned short* __restrict__ Al0,
        int ldA, long bsA,
        const unsigned short* __restrict__ Bh0, const unsigned short* __restrict__ Bl0,
        int ldB, long bsB,
        float* __restrict__ Cm, int ldc, long bsC,
        int K, const float* __restrict__ d2, const float* __restrict__ bnp,
        int Nn, int mode, int npass,
        float* __restrict__ pmax, float* __restrict__ psum) {
    extern __shared__ __align__(16) char dyn[];
    float* redm = (float*)(dyn + 2 * 4 * GSM_BUF);
    float* reds = redm + 256;

    int tid = threadIdx.x, wid = tid >> 5, lane = tid & 31;
    int bm = blockIdx.y * 128, bn = blockIdx.x * 128, z = blockIdx.z;

    const unsigned short* Ah = Ah0 + (long)z * bsA;
    const unsigned short* Al = Al0 + (long)z * bsA;
    const unsigned short* Bh = Bh0 + (long)z * bsB;
    const unsigned short* Bl = Bl0 + (long)z * bsB;

    int wm = (wid >> 2) * 64, wn = (wid & 3) * 32;
    int a_r = lane & 15, a_kh = lane >> 4;
    int b_n = (lane & 7) + ((lane >> 4) << 3), b_kh = (lane >> 3) & 1;

    uint32_t ub = smem_u32(dyn);

    int r0 = tid >> 2, ci0 = tid & 3;
    int r1 = (tid + 256) >> 2, ci1 = (tid + 256) & 3;
    int ph0 = r0 * 64 + ((ci0 ^ ((r0 >> 1) & 3)) * 16);
    int ph1 = r1 * 64 + ((ci1 ^ ((r1 >> 1) & 3)) * 16);

    int nch = K >> 5;

#define LOAD_CHUNK(bufi, k0_) do { \
    uint32_t o = ub + (bufi) * 4 * GSM_BUF; \
    long gA0 = (long)(bm + r0) * ldA + (k0_) + ci0 * 8; \
    long gA1 = (long)(bm + r1) * ldA + (k0_) + ci1 * 8; \
    long gB0 = (long)(bn + r0) * ldB + (k0_) + ci0 * 8; \
    long gB1 = (long)(bn + r1) * ldB + (k0_) + ci1 * 8; \
    CPA16(o + ph0, Ah + gA0);                 CPA16(o + ph1, Ah + gA1); \
    CPA16(o + 2 * GSM_BUF + ph0, Bh + gB0);   CPA16(o + 2 * GSM_BUF + ph1, Bh + gB1); \
    CPA16(o + GSM_BUF + ph0, Al + gA0);       CPA16(o + GSM_BUF + ph1, Al + gA1); \
    CPA16(o + 3 * GSM_BUF + ph0, Bl + gB0);   CPA16(o + 3 * GSM_BUF + ph1, Bl + gB1); \
    CPA_COMMIT(); \
} while (0)

    float acc[4][4][4] = {};

    LOAD_CHUNK(0, 0);
    for (int ch = 0; ch < nch; ch++) {
        if (ch + 1 < nch) {
            LOAD_CHUNK((ch + 1) & 1, (ch + 1) << 5);
            CPA_WAIT1();
        } else {
            CPA_WAIT0();
        }
        __syncthreads();
        uint32_t o = ub + (ch & 1) * 4 * GSM_BUF;
        uint32_t sAh = o, sAl = o + GSM_BUF, sBh = o + 2 * GSM_BUF, sBl = o + 3 * GSM_BUF;
#pragma unroll
        for (int s = 0; s < 2; s++) {
            uint32_t af[4][4], bfh[2][4], bfl[2][4];
#pragma unroll
            for (int mt = 0; mt < 4; mt++) {
                int row = wm + mt * 16 + a_r;
                int chh = 2 * s + a_kh;
                LDSM4(af[mt], sAh + row * 64 + ((chh ^ ((row >> 1) & 3)) * 16));
            }
#pragma unroll
            for (int g = 0; g < 2; g++) {
                int row = wn + g * 16 + b_n;
                int chh = 2 * s + b_kh;
                LDSM4(bfh[g], sBh + row * 64 + ((chh ^ ((row >> 1) & 3)) * 16));
            }
#pragma unroll
            for (int mt = 0; mt < 4; mt++)
#pragma unroll
                for (int nt = 0; nt < 4; nt++)
                    MMA16816(acc[mt][nt], af[mt], bfh[nt >> 1][(nt & 1) * 2], bfh[nt >> 1][(nt & 1) * 2 + 1]);
#pragma unroll
            for (int g = 0; g < 2; g++) {
                int row = wn + g * 16 + b_n;
                int chh = 2 * s + b_kh;
                LDSM4(bfl[g], sBl + row * 64 + ((chh ^ ((row >> 1) & 3)) * 16));
            }
#pragma unroll
            for (int mt = 0; mt < 4; mt++)
#pragma unroll
                for (int nt = 0; nt < 4; nt++)
                    MMA16816(acc[mt][nt], af[mt], bfl[nt >> 1][(nt & 1) * 2], bfl[nt >> 1][(nt & 1) * 2 + 1]);
            if (npass > 2) {
#pragma unroll
                for (int mt = 0; mt < 4; mt++) {
                    int row = wm + mt * 16 + a_r;
                    int chh = 2 * s + a_kh;
                    LDSM4(af[mt], sAl + row * 64 + ((chh ^ ((row >> 1) & 3)) * 16));
                }
#pragma unroll
                for (int mt = 0; mt < 4; mt++)
#pragma unroll
                    for (int nt = 0; nt < 4; nt++)
                        MMA16816(acc[mt][nt], af[mt], bfh[nt >> 1][(nt & 1) * 2], bfh[nt >> 1][(nt & 1) * 2 + 1]);
            }
        }
        __syncthreads();
    }

    if (mode == 3) {
        float cmax[8], csum[8];
#pragma unroll
        for (int q = 0; q < 8; q++) { cmax[q] = -INFINITY; csum[q] = 0.f; }
#pragma unroll
        for (int mt = 0; mt < 4; mt++)
#pragma unroll
            for (int h = 0; h < 2; h++)
#pragma unroll
                for (int nt = 0; nt < 4; nt++)
#pragma unroll
                    for (int j = 0; j < 2; j++) {
                        int col = bn + wn + nt * 8 + (lane & 3) * 2 + j;
                        float v = acc[mt][nt][h * 2 + j];
                        float gg = bnp[col], be = bnp[Nn + col];
                        float mm = bnp[2 * Nn + col], vv = bnp[3 * Nn + col];
                        v = (v - mm) * (gg * rsqrtf(vv + EPS)) + be;
                        v = v > 0.f ? v : SLOPE * v;
                        int q = nt * 2 + j;
                        cmax[q] = fmaxf(cmax[q], v);
                        csum[q] += v;
                    }
#pragma unroll
        for (int q = 0; q < 8; q++) {
#pragma unroll
            for (int off = 4; off < 32; off <<= 1) {
                cmax[q] = fmaxf(cmax[q], __shfl_xor_sync(0xffffffffu, cmax[q], off));
                csum[q] += __shfl_xor_sync(0xffffffffu, csum[q], off);
            }
        }
        if ((lane >> 2) == 0) {
            int g = wid >> 2;
#pragma unroll
            for (int nt = 0; nt < 4; nt++)
#pragma unroll
                for (int j = 0; j < 2; j++) {
                    int cl = wn + nt * 8 + (lane & 3) * 2 + j;
                    redm[g * 128 + cl] = cmax[nt * 2 + j];
                    reds[g * 128 + cl] = csum[nt * 2 + j];
                }
        }
        __syncthreads();
        if (tid < 128) {
            pmax[(long)blockIdx.y * 1024 + bn + tid] = fmaxf(redm[tid], redm[128 + tid]);
            psum[(long)blockIdx.y * 1024 + bn + tid] = reds[tid] + reds[128 + tid];
        }
        return;
    }

    float* Cb = Cm + (long)z * bsC;
#pragma unroll
    for (int mt = 0; mt < 4; mt++) {
        int rr = bm + wm + mt * 16 + (lane >> 2);
#pragma unroll
        for (int h = 0; h < 2; h++) {
            int row = rr + h * 8;
#pragma unroll
            for (int nt = 0; nt < 4; nt++) {
                int col = bn + wn + nt * 8 + (lane & 3) * 2;
                float v0 = acc[mt][nt][h * 2];
                float v1 = acc[mt][nt][h * 2 + 1];
                if (mode == 1) {
                    const float* dd = d2 + (long)z * NPTS;
                    v0 = 2.f * v0 - dd[col];
                    v1 = 2.f * v1 - dd[col + 1];
                } else if (mode == 2) {
                    float gg = bnp[col], be = bnp[Nn + col];
                    float mm = bnp[2 * Nn + col], vv = bnp[3 * Nn + col];
                    v0 = (v0 - mm) * (gg * rsqrtf(vv + EPS)) + be;
                    v0 = v0 > 0.f ? v0 : SLOPE * v0;
                    gg = bnp[col + 1]; be = bnp[Nn + col + 1];
                    mm = bnp[2 * Nn + col + 1]; vv = bnp[3 * Nn + col + 1];
                    v1 = (v1 - mm) * (gg * rsqrtf(vv + EPS)) + be;
                    v1 = v1 > 0.f ? v1 : SLOPE * v1;
                }
                *(float2*)&Cb[(long)row * ldc + col] = make_float2(v0, v1);
            }
        }
    }
}

// ======================= pool reduce =======================
__global__ void pool_reduce(const float* __restrict__ pmax, const float* __restrict__ psum,
                            float* __restrict__ gb) {
    int c = blockIdx.x * 256 + threadIdx.x;
    int b = blockIdx.y;
    float m = -INFINITY, s = 0.f;
#pragma unroll
    for (int i = 0; i < 16; i++) {
        int by = b * 16 + i;
        m = fmaxf(m, pmax[(long)by * 1024 + c]);
        s += psum[(long)by * 1024 + c];
    }
    gb[b * 2048 + c] = m;
    gb[b * 2048 + 1024 + c] = s * (1.0f / NPTS);
}

// ======================= fused layer-1 YZ (K=3) =======================
__global__ __launch_bounds__(256) void l1yz_d2(
        const float* __restrict__ x, const float* __restrict__ w1,
        float* __restrict__ YZ) {
    __shared__ float wf[128][3];
    int tid = threadIdx.x;
    if (tid < 128) {
        int o = tid & 63;
        if (tid < 64) {
            wf[tid][0] = w1[o * 6 + 0];
            wf[tid][1] = w1[o * 6 + 1];
            wf[tid][2] = w1[o * 6 + 2];
        } else {
            wf[tid][0] = w1[o * 6 + 3] - w1[o * 6 + 0];
            wf[tid][1] = w1[o * 6 + 4] - w1[o * 6 + 1];
            wf[tid][2] = w1[o * 6 + 5] - w1[o * 6 + 2];
        }
    }
    __syncthreads();
    long i = (long)blockIdx.x * 256 + tid;
    int n = (int)(i >> 7), o = (int)(i & 127);
    float x0 = x[n * 3], x1 = x[n * 3 + 1], x2 = x[n * 3 + 2];
    YZ[i] = x0 * wf[o][0] + x1 * wf[o][1] + x2 * wf[o][2];
}

// ======================= fused layer-1 KNN =======================
#define TOPK_L1_SMEM ((8 * 2048 + 3 * 2048) * 4)
__global__ __launch_bounds__(256) void topk_l1(const float* __restrict__ xg,
                                               int* __restrict__ idxo) {
    extern __shared__ float sm[];
    float* sv_all = sm;
    float* cx = sm + 8 * 2048;
    float* cy = cx + 2048;
    float* cz = cy + 2048;
    int warp = threadIdx.x >> 5, lane = threadIdx.x & 31;
    int b = blockIdx.y;
    int row = blockIdx.x * 8 + warp;
    const float* xb = xg + (long)b * NPTS * 3;
    for (int j = threadIdx.x; j < NPTS; j += 256) {
        cx[j] = xb[j * 3];
        cy[j] = xb[j * 3 + 1];
        cz[j] = xb[j * 3 + 2];
    }
    __syncthreads();
    float* sv = sv_all + warp * 2048;
    float r0 = cx[row], r1 = cy[row], r2 = cz[row];

    float gmax[8];
    int gj[8];
#pragma unroll
    for (int g = 0; g < 8; g++) {
        float bm = -INFINITY;
        int bj = g * 8;
#pragma unroll
        for (int e = 0; e < 8; e++) {
            int j = g * 8 + e;
            int col = j * 32 + lane;
            float c0 = cx[col], c1 = cy[col], c2 = cz[col];
            float dot = fmaf(r2, c2, fmaf(r1, c1, r0 * c0));
            float dd = fmaf(c2, c2, fmaf(c1, c1, c0 * c0));
            float v = 2.f * dot - dd;
            sv[col] = v;
            if (v > bm) { bm = v; bj = j; }
        }
        gmax[g] = bm; gj[g] = bj;
    }

    for (int it = 0; it < KNN; it++) {
        float best = gmax[0];
        int bj = gj[0];
#pragma unroll
        for (int g = 1; g < 8; g++)
            if (gmax[g] > best) { best = gmax[g]; bj = gj[g]; }
        int bidx = bj * 32 + lane;
        float wb = best;
        int wi = bidx;
#pragma unroll
        for (int o = 16; o; o >>= 1) {
            float ov = __shfl_down_sync(0xffffffffu, wb, o);
            int oi = __shfl_down_sync(0xffffffffu, wi, o);
            if (ov > wb || (ov == wb && oi < wi)) { wb = ov; wi = oi; }
        }
        wi = __shfl_sync(0xffffffffu, wi, 0);
        if (lane == 0) idxo[((long)b * NPTS + row) * KNN + it] = wi;
        if ((wi & 31) == lane) {
            int j = wi >> 5;
            int g = j >> 3;
            sv[j * 32 + lane] = -INFINITY;
            float bm = -INFINITY;
            int bjn = g * 8;
            for (int e = 0; e < 8; e++) {
                int jj = g * 8 + e;
                float v = sv[jj * 32 + lane];
                if (v > bm) { bm = v; bjn = jj; }
            }
#pragma unroll
            for (int gg = 0; gg < 8; gg++)
                if (gg == g) { gmax[gg] = bm; gj[gg] = bjn; }
        }
    }
}

// ======================= d2 + split (weights only) =======================
__global__ void d2split_kernel(const float* __restrict__ src, int ld, int C, int rows,
                               unsigned short* __restrict__ hi, unsigned short* __restrict__ lo,
                               float* __restrict__ d2) {
    int row = blockIdx.x * 8 + (threadIdx.x >> 5);
    int lane = threadIdx.x & 31;
    if (row >= rows) return;
    const float* xr = src + (long)row * ld;
    float s = 0.f;
    for (int c = lane; c < C; c += 32) {
        float v = xr[c];
        s += v * v;
        __half h = __float2half_rn(v);
        __half l = __float2half_rn(v - __half2float(h));
        hi[(long)row * C + c] = *(unsigned short*)&h;
        lo[(long)row * C + c] = *(unsigned short*)&l;
    }
    if (d2) {
#pragma unroll
        for (int o = 16; o; o >>= 1) s += __shfl_xor_sync(0xffffffffu, s, o);
        if (lane == 0) d2[row] = s;
    }
}

__global__ void make_weff_split(const float* __restrict__ w, int O, int C,
                                unsigned short* __restrict__ hi, unsigned short* __restrict__ lo) {
    int i = blockIdx.x * blockDim.x + threadIdx.x;
    if (i >= 2 * O * C) return;
    int row = i / C, c = i % C;
    float v;
    if (row < O) v = w[row * 2 * C + c];
    else { int o = row - O; v = w[o * 2 * C + C + c] - w[o * 2 * C + c]; }
    __half h = __float2half_rn(v);
    __half l = __float2half_rn(v - __half2float(h));
    hi[i] = *(unsigned short*)&h;
    lo[i] = *(unsigned short*)&l;
}

// ---------------- top-k (layers 2-4) ----------------
#define TOPK_SMEM (8 * 2048 * 4)
__global__ __launch_bounds__(256) void topk_kernel(const float* __restrict__ S,
                                                   int* __restrict__ idxo) {
    extern __shared__ float sv_all[];
    int warp = threadIdx.x >> 5, lane = threadIdx.x & 31;
    int row = blockIdx.x * 8 + warp;
    float* sv = sv_all + warp * 2048;
    const float* s = S + (long)row * NPTS;

    float gmax[8];
    int gj[8];
#pragma unroll
    for (int g = 0; g < 8; g++) {
        float bm = -INFINITY;
        int bj = g * 8;
#pragma unroll
        for (int e = 0; e < 8; e++) {
            int j = g * 8 + e;
            float v = s[j * 32 + lane];
            sv[j * 32 + lane] = v;
            if (v > bm) { bm = v; bj = j; }
        }
        gmax[g] = bm; gj[g] = bj;
    }

    for (int it = 0; it < KNN; it++) {
        float best = gmax[0];
        int bj = gj[0];
#pragma unroll
        for (int g = 1; g < 8; g++)
            if (gmax[g] > best) { best = gmax[g]; bj = gj[g]; }
        int bidx = bj * 32 + lane;
        float wb = best;
        int wi = bidx;
#pragma unroll
        for (int o = 16; o; o >>= 1) {
            float ov = __shfl_down_sync(0xffffffffu, wb, o);
            int oi = __shfl_down_sync(0xffffffffu, wi, o);
            if (ov > wb || (ov == wb && oi < wi)) { wb = ov; wi = oi; }
        }
        wi = __shfl_sync(0xffffffffu, wi, 0);
        if (lane == 0) idxo[(long)row * KNN + it] = wi;
        if ((wi & 31) == lane) {
            int j = wi >> 5;
            int g = j >> 3;
            sv[j * 32 + lane] = -INFINITY;
            float bm = -INFINITY;
            int bjn = g * 8;
            for (int e = 0; e < 8; e++) {
                int jj = g * 8 + e;
                float v = sv[jj * 32 + lane];
                if (v > bm) { bm = v; bjn = jj; }
            }
#pragma unroll
            for (int gg = 0; gg < 8; gg++)
                if (gg == g) { gmax[gg] = bm; gj[gg] = bjn; }
        }
    }
}

// ---------------- gather + max + bn + act + fp16 split + d2 emit ----------------
__global__ void gather_max(const float* __restrict__ YZ, int twoO,
                           const int* __restrict__ idxi,
                           const float* __restrict__ bnp,
                           unsigned short* __restrict__ hi, unsigned short* __restrict__ lo,
                           int outoff, float* __restrict__ d2, int O) {
    int n = blockIdx.x, b = blockIdx.y, o = threadIdx.x;
    __shared__ int si[KNN];
    __shared__ float red[8];
    if (o < KNN) si[o] = idxi[((long)b * NPTS + n) * KNN + o];
    __syncthreads();
    const float* Yb = YZ + (long)b * NPTS * twoO;
    float m = -INFINITY;
#pragma unroll 4
    for (int k = 0; k < KNN; k++) m = fmaxf(m, Yb[(long)si[k] * twoO + o]);
    float z = Yb[(long)n * twoO + O + o];
    float t = m + z;
    float gg = bnp[o], be = bnp[O + o], mm = bnp[2 * O + o], vv = bnp[3 * O + o];
    float v = (t - mm) * (gg * rsqrtf(vv + EPS)) + be;
    v = v > 0.f ? v : SLOPE * v;
    long base = ((long)b * NPTS + n) * 512 + outoff + o;
    __half h = __float2half_rn(v);
    __half l2 = __float2half_rn(v - __half2float(h));
    hi[base] = *(unsigned short*)&h;
    lo[base] = *(unsigned short*)&l2;
    if (d2) {
        float s = v * v;
#pragma unroll
        for (int off = 16; off; off >>= 1) s += __shfl_down_sync(0xffffffffu, s, off);
        if ((o & 31) == 0) red[o >> 5] = s;
        __syncthreads();
        if (o == 0) {
            float tot = 0.f;
            for (int w = 0; w < (O >> 5); w++) tot += red[w];
            d2[b * NPTS + n] = tot;
        }
    }
}

// ---------------- small FC ----------------
__global__ void fc_kernel(const float* __restrict__ in, int K,
                          const float* __restrict__ W,
                          const float* __restrict__ bias,
                          const float* __restrict__ bnp, int useAct,
                          float* __restrict__ out, int O) {
    int o = blockIdx.x, b = blockIdx.y, t = threadIdx.x;
    const float* xr = in + (long)b * K;
    const float* wr = W + (long)o * K;
    float s = 0.f;
    for (int k = t; k < K; k += 128) s += xr[k] * wr[k];
    __shared__ float red[4];
#pragma unroll
    for (int off = 16; off; off >>= 1) s += __shfl_down_sync(0xffffffffu, s, off);
    if ((t & 31) == 0) red[t >> 5] = s;
    __syncthreads();
    if (t == 0) {
        float tot = red[0] + red[1] + red[2] + red[3];
        if (bias) tot += bias[o];
        if (bnp) {
            float gg = bnp[o], be = bnp[O + o], mm = bnp[2 * O + o], vv = bnp[3 * O + o];
            tot = (tot - mm) * (gg * rsqrtf(vv + EPS)) + be;
        }
        if (useAct) tot = tot > 0.f ? tot : SLOPE * tot;
        out[(long)b * O + o] = tot;
    }
}

extern "C" void kernel_launch(void* const* d_in, const int* in_sizes, int n_in,
                              void* d_out, int out_size) {
    const float* x   = (const float*)d_in[0];
    const float* w1  = (const float*)d_in[2];
    const float* w2  = (const float*)d_in[3];
    const float* w3  = (const float*)d_in[4];
    const float* w4  = (const float*)d_in[5];
    const float* w5  = (const float*)d_in[6];
    const float* wl1 = (const float*)d_in[7];
    const float* wl2 = (const float*)d_in[8];
    const float* bl2 = (const float*)d_in[9];
    const float* wl3 = (const float*)d_in[10];
    const float* bl3 = (const float*)d_in[11];
    const float* bn1 = (const float*)d_in[12];
    const float* bn2 = (const float*)d_in[13];
    const float* bn3 = (const float*)d_in[14];
    const float* bn4 = (const float*)d_in[15];
    const float* bn5 = (const float*)d_in[16];
    const float* bn6 = (const float*)d_in[17];
    const float* bn7 = (const float*)d_in[18];

    float *S, *d2, *YZ, *pmax, *psum, *gb, *h1, *h2;
    int* idx;
    unsigned short *XCh, *XCl, *W5h, *W5l, *Wh, *Wl;
    cudaGetSymbolAddress((void**)&S, g_S);
    cudaGetSymbolAddress((void**)&d2, g_d2);
    cudaGetSymbolAddress((void**)&idx, g_idx);
    cudaGetSymbolAddress((void**)&YZ, g_YZ);
    cudaGetSymbolAddress((void**)&pmax, g_pmax);
    cudaGetSymbolAddress((void**)&psum, g_psum);
    cudaGetSymbolAddress((void**)&gb, g_g);
    cudaGetSymbolAddress((void**)&h1, g_h1);
    cudaGetSymbolAddress((void**)&h2, g_h2);
    cudaGetSymbolAddress((void**)&XCh, g_XCh);
    cudaGetSymbolAddress((void**)&XCl, g_XCl);
    cudaGetSymbolAddress((void**)&W5h, g_W5h);
    cudaGetSymbolAddress((void**)&W5l, g_W5l);
    cudaGetSymbolAddress((void**)&Wh, g_Wh);
    cudaGetSymbolAddress((void**)&Wl, g_Wl);

    // streams/events created once on the (uncaptured) correctness call
    static cudaStream_t s1 = nullptr;
    static cudaEvent_t evFork = nullptr, evJoin = nullptr, evW = nullptr;
    if (!s1) {
        cudaStreamCreateWithFlags(&s1, cudaStreamNonBlocking);
        cudaEventCreateWithFlags(&evFork, cudaEventDisableTiming);
        cudaEventCreateWithFlags(&evJoin, cudaEventDisableTiming);
        cudaEventCreateWithFlags(&evW, cudaEventDisableTiming);
        cudaFuncSetAttribute(gemm_mma, cudaFuncAttributeMaxDynamicSharedMemorySize, GSM_TOTAL);
        cudaFuncSetAttribute(topk_kernel, cudaFuncAttributeMaxDynamicSharedMemorySize, TOPK_SMEM);
        cudaFuncSetAttribute(topk_l1, cudaFuncAttributeMaxDynamicSharedMemorySize, TOPK_L1_SMEM);
    }

    const int TOTAL = BSZ * NPTS;  // 16384
    const int WOFF[3] = {0, 8192, 24576};

    // ---------- fork s1; weight prep + layer-1 YZ run on s1 ----------
    cudaEventRecord(evFork, 0);
    cudaStreamWaitEvent(s1, evFork, 0);
    make_weff_split<<<(2 * 64 * 64 + 255) / 256, 256, 0, s1>>>(w2, 64, 64, Wh + WOFF[0], Wl + WOFF[0]);
    make_weff_split<<<(2 * 128 * 64 + 255) / 256, 256, 0, s1>>>(w3, 128, 64, Wh + WOFF[1], Wl + WOFF[1]);
    make_weff_split<<<(2 * 256 * 128 + 255) / 256, 256, 0, s1>>>(w4, 256, 128, Wh + WOFF[2], Wl + WOFF[2]);
    d2split_kernel<<<1024 / 8, 256, 0, s1>>>(w5, 512, 512, 1024, W5h, W5l, nullptr);
    cudaEventRecord(evW, s1);
    l1yz_d2<<<(int)(((long)TOTAL * 128) / 256), 256, 0, s1>>>(x, w1, YZ);
    cudaEventRecord(evJoin, s1);

    // ---------- layer 1 on s0: topk runs concurrently with s1 work ----------
    topk_l1<<<dim3(NPTS / 8, BSZ), 256, TOPK_L1_SMEM>>>(x, idx);
    cudaStreamWaitEvent(0, evJoin, 0);
    gather_max<<<dim3(NPTS, BSZ), 64>>>(YZ, 128, idx, bn1, XCh, XCl, 0, d2, 64);

    // ---------- layers 2-4: gram+topk on s0, YZ on s1 (forked after gather) ----------
    struct L { int coff, C, O, outoff, woff, yznp; const float* bn; int emitd2; };
    L Ls[3] = { {0, 64, 64, 64, WOFF[0], 3, bn2, 1},
                {64, 64, 128, 128, WOFF[1], 3, bn3, 1},
                {128, 128, 256, 256, WOFF[2], 2, bn4, 0} };
    for (int l = 0; l < 3; l++) {
        const L& c = Ls[l];
        cudaEventRecord(evFork, 0);
        cudaStreamWaitEvent(s1, evFork, 0);
        gemm_mma<<<dim3(2 * c.O / 128, TOTAL / 128, 1), 256, GSM_TOTAL, s1>>>(
            XCh + c.coff, XCl + c.coff, 512, 0,
            Wh + c.woff, Wl + c.woff, c.C, 0,
            YZ, 2 * c.O, 0, c.C, nullptr, nullptr, 2 * c.O, 0, c.yznp, nullptr, nullptr);
        cudaEventRecord(evJoin, s1);

        gemm_mma<<<dim3(16, 16, BSZ), 256, GSM_TOTAL>>>(
            XCh + c.coff, XCl + c.coff, 512, (long)NPTS * 512,
            XCh + c.coff, XCl + c.coff, 512, (long)NPTS * 512,
            S, NPTS, (long)NPTS * NPTS, c.C, d2, nullptr, NPTS, 1, 3, nullptr, nullptr);
        topk_kernel<<<TOTAL / 8, 256, TOPK_SMEM>>>(S, idx);
        cudaStreamWaitEvent(0, evJoin, 0);
        gather_max<<<dim3(NPTS, BSZ), c.O>>>(YZ, 2 * c.O, idx, c.bn,
                                             XCh, XCl, c.outoff, c.emitd2 ? d2 : nullptr, c.O);
    }

    // ---------- x5 GEMM with fused pool partials (npass=2) ----------
    cudaStreamWaitEvent(0, evW, 0);
    gemm_mma<<<dim3(8, TOTAL / 128, 1), 256, GSM_TOTAL>>>(
        XCh, XCl, 512, 0, W5h, W5l, 512, 0,
        nullptr, 1024, 0, 512, nullptr, bn5, 1024, 3, 2, pmax, psum);
    pool_reduce<<<dim3(4, BSZ), 256>>>(pmax, psum, gb);

    // ---------- FC stack ----------
    fc_kernel<<<dim3(512, BSZ), 128>>>(gb, 2048, wl1, nullptr, bn6, 1, h1, 512);
    fc_kernel<<<dim3(256, BSZ), 128>>>(h1, 512, wl2, bl2, bn7, 1, h2, 256);
    fc_kernel<<<dim3(40, BSZ), 128>>>(h2, 256, wl3, bl3, nullptr, 0, (float*)d_out, 40);
}